// round 3
// baseline (speedup 1.0000x reference)
#include <cuda_runtime.h>
#include <math.h>

typedef unsigned long long ull;

#define BB   8
#define FHH  8
#define NN   2048
#define TINN 5
#define HH1  32
#define HH2  64
#define KXX  40      // TIN*FH
#define NEGV -9e15f
#define SPLIT 8
#define TI    128     // gat i-tile rows
#define ROWS_TOT (BB*NN)

// ---------------- scratch (device globals; no allocation allowed) ----------
__device__ float g_h1[BB*NN*HH1];   // [t][n][j]
__device__ float g_hs[BB*NN*HH2];   // [t][n][u]
__device__ float g_Wh[BB*NN*HH2];   // [t][n][c]
__device__ float g_s [BB*NN];
__device__ float g_d [BB*NN];
__device__ float g_pm  [SPLIT*ROWS_TOT];          // partial max
__device__ float g_pl  [SPLIT*ROWS_TOT];          // partial l
__device__ float g_pacc[SPLIT*ROWS_TOT*HH2];      // partial unnormalized acc

// ---------------- packed f32x2 helpers (Blackwell) --------------------------
__device__ __forceinline__ ull pack2(float lo, float hi) {
    ull r; asm("mov.b64 %0, {%1, %2};" : "=l"(r) : "f"(lo), "f"(hi)); return r;
}
__device__ __forceinline__ void unpack2(ull v, float& lo, float& hi) {
    asm("mov.b64 {%0, %1}, %2;" : "=f"(lo), "=f"(hi) : "l"(v));
}
__device__ __forceinline__ ull ffma2(ull a, ull b, ull c) {
    ull r; asm("fma.rn.f32x2 %0, %1, %2, %3;" : "=l"(r) : "l"(a), "l"(b), "l"(c)); return r;
}
__device__ __forceinline__ ull fmul2(ull a, ull b) {
    ull r; asm("mul.rn.f32x2 %0, %1, %2;" : "=l"(r) : "l"(a), "l"(b)); return r;
}

// ============================================================================
// Kernel 1: h1[t,n,k] = elu( sum x[t,n,idx] * W1[k,idx] + b1[k] )
// ============================================================================
__global__ void k_h1(const float* __restrict__ hist,
                     const float* __restrict__ W1,
                     const float* __restrict__ b1) {
    __shared__ float w1s[KXX*HH1];   // transposed: [idx][k]
    for (int i = threadIdx.x; i < HH1*KXX; i += 256) {
        int k = i / KXX, idx = i % KXX;
        w1s[idx*HH1 + k] = W1[i];
    }
    __syncthreads();
    int row = blockIdx.x * 8 + (threadIdx.x >> 5);   // over B*N = 16384
    int k   = threadIdx.x & 31;
    int t = row / NN, n = row % NN;
    float acc = b1[k];
    #pragma unroll
    for (int tt = 0; tt < TINN; tt++) {
        #pragma unroll
        for (int f = 0; f < FHH; f++) {
            float x = hist[((t*FHH + f)*NN + n)*TINN + tt];
            acc = fmaf(x, w1s[(tt*FHH + f)*HH1 + k], acc);
        }
    }
    acc = acc > 0.f ? acc : expm1f(acc);
    g_h1[row*HH1 + k] = acc;
}

// ============================================================================
// Kernel 2: LSTM. 128 blocks x 256 threads; block = 16 nodes.
// thread: lane -> unit pair u0=lane*2 (all 4 gates), wg=tid>>5 -> 2 nodes.
// weights re-laid-out so each thread reads its 8 gate-weights with 2 LDS.128.
// ============================================================================
__global__ void k_lstm(const float* __restrict__ W_ih, const float* __restrict__ W_hh,
                       const float* __restrict__ b_ih, const float* __restrict__ b_hh) {
    extern __shared__ float sm[];
    float* wih = sm;                  // [32][256]  [j][lane*8 + gt*2 + q]
    float* whh = wih + 32*256;        // [64][256]
    float* bs  = whh + 64*256;        // [256]      [lane*8 + gt*2 + q]
    float* h1s = bs + 256;            // [32][17]
    float* hsh = h1s + 32*17;         // [64][17]

    int tid = threadIdx.x;
    for (int i = tid; i < 32*256; i += 256) {
        int j = i >> 8, r = i & 255;
        int ln = r >> 3, o = r & 7, gt = o >> 1, q = o & 1;
        wih[i] = W_ih[(gt*64 + ln*2 + q)*HH1 + j];
    }
    for (int i = tid; i < 64*256; i += 256) {
        int j = i >> 8, r = i & 255;
        int ln = r >> 3, o = r & 7, gt = o >> 1, q = o & 1;
        whh[i] = W_hh[(gt*64 + ln*2 + q)*HH2 + j];
    }
    {
        int ln = tid >> 3, o = tid & 7, gt = o >> 1, q = o & 1;
        bs[tid] = b_ih[gt*64 + ln*2 + q] + b_hh[gt*64 + ln*2 + q];
    }
    for (int i = tid; i < 64*17; i += 256) hsh[i] = 0.f;

    int lane = tid & 31;
    int wg   = tid >> 5;
    int m0   = wg * 2;            // this thread's 2 nodes
    int u0   = lane * 2;
    int node0 = blockIdx.x * 16;

    float c[2][2] = {{0.f,0.f},{0.f,0.f}};

    for (int t = 0; t < BB; t++) {
        __syncthreads();
        for (int i = tid; i < 512; i += 256) {
            int mm = i >> 5, j = i & 31;
            h1s[j*17 + mm] = g_h1[(t*NN + node0 + mm)*HH1 + j];
        }
        __syncthreads();

        ull acc[2][4];
        #pragma unroll
        for (int nd = 0; nd < 2; nd++)
            #pragma unroll
            for (int gt = 0; gt < 4; gt++)
                acc[nd][gt] = *(const ull*)&bs[lane*8 + gt*2];

        #pragma unroll 8
        for (int j = 0; j < 32; j++) {
            ull hv2[2];
            hv2[0] = pack2(h1s[j*17 + m0],     h1s[j*17 + m0]);
            hv2[1] = pack2(h1s[j*17 + m0 + 1], h1s[j*17 + m0 + 1]);
            ulonglong2 wA = *(const ulonglong2*)&wih[j*256 + lane*8];      // gt0, gt1
            ulonglong2 wB = *(const ulonglong2*)&wih[j*256 + lane*8 + 4];  // gt2, gt3
            #pragma unroll
            for (int nd = 0; nd < 2; nd++) {
                acc[nd][0] = ffma2(wA.x, hv2[nd], acc[nd][0]);
                acc[nd][1] = ffma2(wA.y, hv2[nd], acc[nd][1]);
                acc[nd][2] = ffma2(wB.x, hv2[nd], acc[nd][2]);
                acc[nd][3] = ffma2(wB.y, hv2[nd], acc[nd][3]);
            }
        }
        #pragma unroll 8
        for (int j = 0; j < 64; j++) {
            ull hv2[2];
            hv2[0] = pack2(hsh[j*17 + m0],     hsh[j*17 + m0]);
            hv2[1] = pack2(hsh[j*17 + m0 + 1], hsh[j*17 + m0 + 1]);
            ulonglong2 wA = *(const ulonglong2*)&whh[j*256 + lane*8];
            ulonglong2 wB = *(const ulonglong2*)&whh[j*256 + lane*8 + 4];
            #pragma unroll
            for (int nd = 0; nd < 2; nd++) {
                acc[nd][0] = ffma2(wA.x, hv2[nd], acc[nd][0]);
                acc[nd][1] = ffma2(wA.y, hv2[nd], acc[nd][1]);
                acc[nd][2] = ffma2(wB.x, hv2[nd], acc[nd][2]);
                acc[nd][3] = ffma2(wB.y, hv2[nd], acc[nd][3]);
            }
        }
        __syncthreads();   // all reads of old hsh done
        #pragma unroll
        for (int nd = 0; nd < 2; nd++) {
            float gv[4][2];
            #pragma unroll
            for (int gt = 0; gt < 4; gt++) unpack2(acc[nd][gt], gv[gt][0], gv[gt][1]);
            float hout[2];
            #pragma unroll
            for (int q = 0; q < 2; q++) {
                float ig = 1.f / (1.f + __expf(-gv[0][q]));
                float fg = 1.f / (1.f + __expf(-gv[1][q]));
                float gg = tanhf(gv[2][q]);
                float og = 1.f / (1.f + __expf(-gv[3][q]));
                c[nd][q] = fg * c[nd][q] + ig * gg;
                float h = og * tanhf(c[nd][q]);
                hsh[(u0 + q)*17 + m0 + nd] = h;
                hout[q] = h;
            }
            *(float2*)&g_hs[(t*NN + node0 + m0 + nd)*HH2 + u0] =
                make_float2(hout[0], hout[1]);
        }
    }
}

// ============================================================================
// Kernel 3: Wh = hs @ Wg ; s = Wh.a_src ; d = Wh.a_dst
// ============================================================================
__global__ void k_wh(const float* __restrict__ Wg,
                     const float* __restrict__ a_src,
                     const float* __restrict__ a_dst) {
    __shared__ float wgs[64*64];
    __shared__ float hss[64*17];
    __shared__ float ps[16*17];
    __shared__ float pd[16*17];
    int tid = threadIdx.x;
    int row0 = blockIdx.x * 16;
    for (int i = tid; i < 4096; i += 256) wgs[i] = Wg[i];
    for (int i = tid; i < 1024; i += 256) {
        int mm = i >> 6, u = i & 63;
        hss[u*17 + mm] = g_hs[(row0 + mm)*HH2 + u];
    }
    __syncthreads();
    int m  = tid >> 4;
    int cq = tid & 15;
    int c0 = cq * 4;
    ull acc0 = 0ull, acc1 = 0ull;
    #pragma unroll 8
    for (int u = 0; u < 64; u++) {
        float hv = hss[u*17 + m];
        ull hv2 = pack2(hv, hv);
        acc0 = ffma2(*(const ull*)&wgs[u*64 + c0],     hv2, acc0);
        acc1 = ffma2(*(const ull*)&wgs[u*64 + c0 + 2], hv2, acc1);
    }
    float wh[4];
    unpack2(acc0, wh[0], wh[1]);
    unpack2(acc1, wh[2], wh[3]);
    *(float4*)&g_Wh[(row0 + m)*HH2 + c0] = make_float4(wh[0], wh[1], wh[2], wh[3]);
    float psum = 0.f, dsum = 0.f;
    #pragma unroll
    for (int q = 0; q < 4; q++) {
        psum = fmaf(wh[q], a_src[c0 + q], psum);
        dsum = fmaf(wh[q], a_dst[c0 + q], dsum);
    }
    ps[m*17 + cq] = psum;
    pd[m*17 + cq] = dsum;
    __syncthreads();
    if (tid < 16) {
        float s = 0.f, d = 0.f;
        #pragma unroll
        for (int q = 0; q < 16; q++) { s += ps[tid*17 + q]; d += pd[tid*17 + q]; }
        g_s[row0 + tid] = s;
        g_d[row0 + tid] = d;
    }
}

// ============================================================================
// Kernel 4: split-K GAT, online masked softmax. grid (16, 8, SPLIT).
// i-tile = 128 rows. Thread register tile 8 rows x 4 cols:
// smem bytes per MAC = 1.5 (vs 3.0 in R2) -> halve L1 pressure.
// ============================================================================
__global__ void __launch_bounds__(256, 2) k_gat(const int* __restrict__ adj) {
    __shared__ float whs[64*64];      // [jj][c]   16KB
    __shared__ float Ps [TI*64];      // [ii][jj]  32KB
    __shared__ float s_sh[TI], m_sh[TI], l_sh[TI], sc_sh[TI];
    __shared__ float d_sh[64];
    int b   = blockIdx.y;
    int i0  = blockIdx.x * TI;
    int sp  = blockIdx.z;
    int tid  = threadIdx.x;
    int lane = tid & 31, w = tid >> 5;

    if (tid < TI) {
        s_sh[tid] = g_s[b*NN + i0 + tid];
        m_sh[tid] = -INFINITY;
        l_sh[tid] = 0.f;
    }

    int ig = tid >> 4;     // 0..15 -> rows ig*8 .. ig*8+7
    int cg = tid & 15;
    int c0 = cg * 4;
    ull acc[8][2];
    #pragma unroll
    for (int q = 0; q < 8; q++) { acc[q][0] = 0ull; acc[q][1] = 0ull; }

    const int* adjb = adj + (size_t)(b*2 + 1) * NN * NN;
    const int JT = (NN/64)/SPLIT;    // j-tiles per block

    for (int jtl = 0; jtl < JT; jtl++) {
        int j0 = (sp * JT + jtl) * 64;
        __syncthreads();                       // prev-iter readers done
        for (int i = tid; i < 4096; i += 256)
            whs[i] = g_Wh[(b*NN + j0)*HH2 + i];
        if (tid < 64) d_sh[tid] = g_d[b*NN + j0 + tid];
        __syncthreads();

        // ---- phase P: warp w owns rows ii = w*16 .. w*16+15 ----------------
        #pragma unroll
        for (int r = 0; r < TI/8; r++) {
            int ii = w*(TI/8) + r;
            int i  = i0 + ii;
            float si = s_sh[ii];
            const int* arow = adjb + (size_t)i * NN + j0;
            int a1 = arow[lane];
            int a2 = arow[lane + 32];
            float v1 = si + d_sh[lane];
            float v2 = si + d_sh[lane + 32];
            float e1 = v1 > 0.f ? v1 : 0.2f * v1;
            float e2 = v2 > 0.f ? v2 : 0.2f * v2;
            e1 = a1 > 0 ? e1 : NEGV;
            e2 = a2 > 0 ? e2 : NEGV;
            float tm = fmaxf(e1, e2);
            #pragma unroll
            for (int o = 16; o > 0; o >>= 1)
                tm = fmaxf(tm, __shfl_xor_sync(0xffffffffu, tm, o));
            float mold = m_sh[ii];
            float mnew = fmaxf(mold, tm);
            float p1 = __expf(e1 - mnew);
            float p2 = __expf(e2 - mnew);
            float psum = p1 + p2;
            #pragma unroll
            for (int o = 16; o > 0; o >>= 1)
                psum += __shfl_xor_sync(0xffffffffu, psum, o);
            if (lane == 0) {
                float scale = __expf(mold - mnew);
                m_sh[ii]  = mnew;
                l_sh[ii]  = l_sh[ii] * scale + psum;
                sc_sh[ii] = scale;
            }
            Ps[ii*64 + lane]      = p1;
            Ps[ii*64 + lane + 32] = p2;
        }
        __syncthreads();

        // ---- accumulate: acc[q] = acc[q]*scale + sum_jj P[ii][jj]*Wh[jj][c]
        #pragma unroll
        for (int q = 0; q < 8; q++) {
            float sc = sc_sh[ig*8 + q];
            ull sc2 = pack2(sc, sc);
            acc[q][0] = fmul2(acc[q][0], sc2);
            acc[q][1] = fmul2(acc[q][1], sc2);
        }
        #pragma unroll 2
        for (int jj = 0; jj < 64; jj++) {
            ull wa = *(const ull*)&whs[jj*64 + c0];
            ull wb = *(const ull*)&whs[jj*64 + c0 + 2];
            #pragma unroll
            for (int q = 0; q < 8; q++) {
                float p = Ps[(ig*8 + q)*64 + jj];
                ull p2 = pack2(p, p);
                acc[q][0] = ffma2(wa, p2, acc[q][0]);
                acc[q][1] = ffma2(wb, p2, acc[q][1]);
            }
        }
    }
    __syncthreads();

    // ---- emit partials -----------------------------------------------------
    if (tid < TI) {
        int r = b*NN + i0 + tid;
        g_pm[sp*ROWS_TOT + r] = m_sh[tid];
        g_pl[sp*ROWS_TOT + r] = l_sh[tid];
    }
    #pragma unroll
    for (int q = 0; q < 8; q++) {
        int ii = ig*8 + q;
        size_t r = (size_t)(sp*ROWS_TOT) + b*NN + i0 + ii;
        float v[4];
        unpack2(acc[q][0], v[0], v[1]);
        unpack2(acc[q][1], v[2], v[3]);
        *(float4*)&g_pacc[r*HH2 + c0] = make_float4(v[0], v[1], v[2], v[3]);
    }
}

// ============================================================================
// Kernel 5: combine split-K partials; final softmax normalize + elu.
// ============================================================================
__global__ void k_comb(float* __restrict__ out) {
    int tid = threadIdx.x;
    int r = blockIdx.x * 4 + (tid >> 6);    // global row 0..16383
    int c = tid & 63;
    float m[SPLIT];
    float mx = -INFINITY;
    #pragma unroll
    for (int s = 0; s < SPLIT; s++) { m[s] = g_pm[s*ROWS_TOT + r]; mx = fmaxf(mx, m[s]); }
    float l = 0.f, val = 0.f;
    #pragma unroll
    for (int s = 0; s < SPLIT; s++) {
        float wgt = __expf(m[s] - mx);
        l   += wgt * g_pl[s*ROWS_TOT + r];
        val += wgt * g_pacc[((size_t)s*ROWS_TOT + r)*HH2 + c];
    }
    float z = val / l;
    out[(size_t)r*HH2 + c] = z > 0.f ? z : expm1f(z);
}

// ============================================================================
extern "C" void kernel_launch(void* const* d_in, const int* in_sizes, int n_in,
                              void* d_out, int out_size) {
    const float* hist  = (const float*)d_in[0];
    const int*   adj   = (const int*)  d_in[1];
    const float* W1    = (const float*)d_in[2];
    const float* b1    = (const float*)d_in[3];
    const float* W_ih  = (const float*)d_in[4];
    const float* W_hh  = (const float*)d_in[5];
    const float* b_ih  = (const float*)d_in[6];
    const float* b_hh  = (const float*)d_in[7];
    const float* Wg    = (const float*)d_in[8];
    const float* a_src = (const float*)d_in[9];
    const float* a_dst = (const float*)d_in[10];
    float* out = (float*)d_out;

    const size_t smem2 = (size_t)(32*256 + 64*256 + 256 + 32*17 + 64*17) * sizeof(float);
    cudaFuncSetAttribute(k_lstm, cudaFuncAttributeMaxDynamicSharedMemorySize, (int)smem2);

    k_h1  <<<2048, 256>>>(hist, W1, b1);
    k_lstm<<<128,  256, smem2>>>(W_ih, W_hh, b_ih, b_hh);
    k_wh  <<<1024, 256>>>(Wg, a_src, a_dst);
    dim3 g4(NN/TI, BB, SPLIT);
    k_gat <<<g4, 256>>>(adj);
    k_comb<<<4096, 256>>>(out);
}

// round 4
// speedup vs baseline: 1.0765x; 1.0765x over previous
#include <cuda_runtime.h>
#include <math.h>

typedef unsigned long long ull;

#define BB   8
#define FHH  8
#define NN   2048
#define TINN 5
#define HH1  32
#define HH2  64
#define KXX  40
#define NEGV -9e15f
#define SPLIT 8
#define TI    128
#define PS    130          // PsT row stride (floats), even for ull reads
#define ROWS_TOT (BB*NN)

// ---------------- scratch ----------------------------------------------------
__device__ float g_h1[BB*NN*HH1];
__device__ float g_wx[BB*NN*4*HH2];            // [t][n][u*4+gt] interleaved, 16.8MB
__device__ float g_hs[BB*NN*HH2];
__device__ float g_Wh[BB*NN*HH2];
__device__ float g_s [BB*NN];
__device__ float g_d [BB*NN];
__device__ float g_pm  [SPLIT*ROWS_TOT];
__device__ float g_pl  [SPLIT*ROWS_TOT];
__device__ float g_pacc[SPLIT*ROWS_TOT*HH2];

// ---------------- f32x2 helpers ----------------------------------------------
__device__ __forceinline__ ull pack2(float lo, float hi) {
    ull r; asm("mov.b64 %0, {%1, %2};" : "=l"(r) : "f"(lo), "f"(hi)); return r;
}
__device__ __forceinline__ void unpack2(ull v, float& lo, float& hi) {
    asm("mov.b64 {%0, %1}, %2;" : "=f"(lo), "=f"(hi) : "l"(v));
}
__device__ __forceinline__ ull ffma2(ull a, ull b, ull c) {
    ull r; asm("fma.rn.f32x2 %0, %1, %2, %3;" : "=l"(r) : "l"(a), "l"(b), "l"(c)); return r;
}
__device__ __forceinline__ ull fmul2(ull a, ull b) {
    ull r; asm("mul.rn.f32x2 %0, %1, %2;" : "=l"(r) : "l"(a), "l"(b)); return r;
}
__device__ __forceinline__ float fsig(float x) {            // sigmoid, MUFU-based
    return __fdividef(1.f, 1.f + __expf(-x));
}
__device__ __forceinline__ float ftanh(float x) {           // tanh = 2*sig(2x)-1
    return fmaf(__fdividef(2.f, 1.f + __expf(-2.f*x)), 1.f, -1.f);
}

// ============================================================================
// Kernel 1: h1 = elu(x @ W1^T + b1)
// ============================================================================
__global__ void k_h1(const float* __restrict__ hist,
                     const float* __restrict__ W1,
                     const float* __restrict__ b1) {
    __shared__ float w1s[KXX*HH1];
    for (int i = threadIdx.x; i < HH1*KXX; i += 256) {
        int k = i / KXX, idx = i % KXX;
        w1s[idx*HH1 + k] = W1[i];
    }
    __syncthreads();
    int row = blockIdx.x * 8 + (threadIdx.x >> 5);
    int k   = threadIdx.x & 31;
    int t = row / NN, n = row % NN;
    float acc = b1[k];
    #pragma unroll
    for (int tt = 0; tt < TINN; tt++)
        #pragma unroll
        for (int f = 0; f < FHH; f++) {
            float x = hist[((t*FHH + f)*NN + n)*TINN + tt];
            acc = fmaf(x, w1s[(tt*FHH + f)*HH1 + k], acc);
        }
    acc = acc > 0.f ? acc : expm1f(acc);
    g_h1[row*HH1 + k] = acc;
}

// ============================================================================
// Kernel 1b: wx[row][u*4+gt] = (b_ih+b_hh)[gt*64+u] + sum_j h1[row][j]*W_ih[gt*64+u][j]
// 2048 blocks x 256 thr, 8 rows/block; thread = 2 rows x (unit u, gates 0-3).
// ============================================================================
__global__ void k_wx(const float* __restrict__ W_ih,
                     const float* __restrict__ b_ih, const float* __restrict__ b_hh) {
    __shared__ float wih[HH1*256];    // [j][u*4+gt]
    __shared__ float bsI[256];        // [u*4+gt]
    __shared__ float h1s[HH1*9];      // [j][r] pad 9
    int tid = threadIdx.x;
    int row0 = blockIdx.x * 8;
    for (int i = tid; i < HH1*256; i += 256) {
        int j = i >> 8, op = i & 255, u = op >> 2, gt = op & 3;
        wih[i] = W_ih[(gt*64 + u)*HH1 + j];
    }
    { int u = tid >> 2, gt = tid & 3; bsI[tid] = b_ih[gt*64+u] + b_hh[gt*64+u]; }
    { int r = tid & 7, j = tid >> 3; h1s[j*9 + r] = g_h1[(row0 + r)*HH1 + j]; }
    __syncthreads();

    int u  = tid & 63;
    int r0 = (tid >> 6) * 2;
    ull acc[2][2];
    ull b0 = *(const ull*)&bsI[u*4], b1v = *(const ull*)&bsI[u*4+2];
    acc[0][0]=b0; acc[0][1]=b1v; acc[1][0]=b0; acc[1][1]=b1v;
    #pragma unroll 8
    for (int j = 0; j < HH1; j++) {
        ulonglong2 wv = *(const ulonglong2*)&wih[j*256 + u*4];
        float ha = h1s[j*9 + r0], hb = h1s[j*9 + r0 + 1];
        ull ha2 = pack2(ha, ha), hb2 = pack2(hb, hb);
        acc[0][0] = ffma2(wv.x, ha2, acc[0][0]);
        acc[0][1] = ffma2(wv.y, ha2, acc[0][1]);
        acc[1][0] = ffma2(wv.x, hb2, acc[1][0]);
        acc[1][1] = ffma2(wv.y, hb2, acc[1][1]);
    }
    #pragma unroll
    for (int nd = 0; nd < 2; nd++) {
        float v0,v1,v2,v3;
        unpack2(acc[nd][0], v0, v1);
        unpack2(acc[nd][1], v2, v3);
        *(float4*)&g_wx[(size_t)(row0 + r0 + nd)*256 + u*4] = make_float4(v0,v1,v2,v3);
    }
}

// ============================================================================
// Kernel 2: recurrent LSTM. 128 blocks x 256 thr, 16 nodes/block.
// thread = (unit u = tid&63) x (nodes nq*4..nq*4+3). Gates interleaved.
// ============================================================================
__global__ void __launch_bounds__(256) k_lstm2(const float* __restrict__ W_hh) {
    extern __shared__ float sm[];
    float* whh = sm;                  // [64][256] interleaved [j][u*4+gt], 64KB
    float* hsh = whh + 64*256;        // [j=unit][node] pad 21

    int tid = threadIdx.x;
    for (int i = tid; i < 64*256; i += 256) {
        int j = i >> 8, op = i & 255, u = op >> 2, gt = op & 3;
        whh[i] = W_hh[(gt*64 + u)*HH2 + j];
    }
    for (int i = tid; i < 64*21; i += 256) hsh[i] = 0.f;

    int u  = tid & 63;
    int nq = tid >> 6;                // 0..3
    int node0 = blockIdx.x * 16 + nq*4;

    float c[4] = {0.f,0.f,0.f,0.f};
    float4 wx4[4];
    #pragma unroll
    for (int n = 0; n < 4; n++)
        wx4[n] = *(const float4*)&g_wx[(size_t)(0*NN + node0 + n)*256 + u*4];

    for (int t = 0; t < BB; t++) {
        __syncthreads();              // hsh from prev step visible
        ull acc[4][2];
        #pragma unroll
        for (int n = 0; n < 4; n++) {
            acc[n][0] = pack2(wx4[n].x, wx4[n].y);
            acc[n][1] = pack2(wx4[n].z, wx4[n].w);
        }
        if (t < BB-1) {
            #pragma unroll
            for (int n = 0; n < 4; n++)
                wx4[n] = *(const float4*)&g_wx[(size_t)((t+1)*NN + node0 + n)*256 + u*4];
        }
        #pragma unroll 4
        for (int j = 0; j < HH2; j++) {
            ulonglong2 wv = *(const ulonglong2*)&whh[j*256 + u*4];
            #pragma unroll
            for (int n = 0; n < 4; n++) {
                float hv = hsh[j*21 + nq*4 + n];
                ull hv2 = pack2(hv, hv);
                acc[n][0] = ffma2(wv.x, hv2, acc[n][0]);
                acc[n][1] = ffma2(wv.y, hv2, acc[n][1]);
            }
        }
        __syncthreads();              // all reads of old hsh done
        #pragma unroll
        for (int n = 0; n < 4; n++) {
            float gi,gf,gg,go;
            unpack2(acc[n][0], gi, gf);
            unpack2(acc[n][1], gg, go);
            c[n] = fsig(gf)*c[n] + fsig(gi)*ftanh(gg);
            float h = fsig(go)*ftanh(c[n]);
            hsh[u*21 + nq*4 + n] = h;
            g_hs[(size_t)(t*NN + node0 + n)*HH2 + u] = h;
        }
    }
}

// ============================================================================
// Kernel 3: Wh = hs @ Wg ; s = Wh.a_src ; d = Wh.a_dst
// ============================================================================
__global__ void k_wh(const float* __restrict__ Wg,
                     const float* __restrict__ a_src,
                     const float* __restrict__ a_dst) {
    __shared__ float wgs[64*64];
    __shared__ float hss[64*17];
    __shared__ float ps[16*17];
    __shared__ float pd[16*17];
    int tid = threadIdx.x;
    int row0 = blockIdx.x * 16;
    for (int i = tid; i < 4096; i += 256) wgs[i] = Wg[i];
    for (int i = tid; i < 1024; i += 256) {
        int mm = i >> 6, u = i & 63;
        hss[u*17 + mm] = g_hs[(row0 + mm)*HH2 + u];
    }
    __syncthreads();
    int m  = tid >> 4;
    int cq = tid & 15;
    int c0 = cq * 4;
    ull acc0 = 0ull, acc1 = 0ull;
    #pragma unroll 8
    for (int u = 0; u < 64; u++) {
        float hv = hss[u*17 + m];
        ull hv2 = pack2(hv, hv);
        acc0 = ffma2(*(const ull*)&wgs[u*64 + c0],     hv2, acc0);
        acc1 = ffma2(*(const ull*)&wgs[u*64 + c0 + 2], hv2, acc1);
    }
    float wh[4];
    unpack2(acc0, wh[0], wh[1]);
    unpack2(acc1, wh[2], wh[3]);
    *(float4*)&g_Wh[(row0 + m)*HH2 + c0] = make_float4(wh[0], wh[1], wh[2], wh[3]);
    float psum = 0.f, dsum = 0.f;
    #pragma unroll
    for (int q = 0; q < 4; q++) {
        psum = fmaf(wh[q], a_src[c0 + q], psum);
        dsum = fmaf(wh[q], a_dst[c0 + q], dsum);
    }
    ps[m*17 + cq] = psum;
    pd[m*17 + cq] = dsum;
    __syncthreads();
    if (tid < 16) {
        float s = 0.f, d = 0.f;
        #pragma unroll
        for (int q = 0; q < 16; q++) { s += ps[tid*17 + q]; d += pd[tid*17 + q]; }
        g_s[row0 + tid] = s;
        g_d[row0 + tid] = d;
    }
}

// ============================================================================
// Kernel 4: split-K GAT. grid (16, 8, SPLIT), 256 thr, 3 CTA/SM.
// P transposed (pairs over rows via LDS.64), Wh duplicated pairs.
// Inner jj: 8 LDS.64 + 16 ffma2, no packs. Thread tile 8 rows x 4 cols.
// ============================================================================
__global__ void __launch_bounds__(256, 3) k_gat(const int* __restrict__ adj) {
    extern __shared__ char smraw[];
    ull*   whs_dup = (ull*)smraw;                       // [jj][c] dup pairs, 32KB
    float* PsT     = (float*)(smraw + 64*64*8);         // [jj][ii] stride PS, 33.3KB
    __shared__ float s_sh[TI], m_sh[TI], l_sh[TI], sc_sh[TI];

    int b   = blockIdx.y;
    int i0  = blockIdx.x * TI;
    int sp  = blockIdx.z;
    int tid  = threadIdx.x;
    int lane = tid & 31, w = tid >> 5;

    if (tid < TI) {
        s_sh[tid] = g_s[b*NN + i0 + tid];
        m_sh[tid] = -INFINITY;
        l_sh[tid] = 0.f;
    }

    int ig = tid >> 4;            // row group: rows ig*8 .. ig*8+7
    int cg = tid & 15;            // cols cg + 16k, k=0..3
    ull acc[4][4];                // [row-pair rp][col k]
    #pragma unroll
    for (int rp = 0; rp < 4; rp++)
        #pragma unroll
        for (int k = 0; k < 4; k++) acc[rp][k] = 0ull;

    const int* adjb = adj + (size_t)(b*2 + 1) * NN * NN;
    const int JT = (NN/64)/SPLIT;

    for (int jtl = 0; jtl < JT; jtl++) {
        int j0 = (sp * JT + jtl) * 64;
        __syncthreads();                                 // prev agg reads done

        // load Wh tile as duplicated pairs
        for (int i = tid; i < 4096; i += 256) {
            float v = g_Wh[(size_t)(b*NN + j0)*HH2 + i];
            whs_dup[i] = pack2(v, v);
        }
        // phase P: warp w owns rows w*16..w*16+15; lane owns jj=2lane,2lane+1
        float2 dv = *(const float2*)&g_d[b*NN + j0 + 2*lane];
        #pragma unroll 4
        for (int r = 0; r < 16; r++) {
            int ii = w*16 + r;
            float si = s_sh[ii];
            int2 av = *(const int2*)&adjb[(size_t)(i0 + ii)*NN + j0 + 2*lane];
            float v0 = si + dv.x, v1 = si + dv.y;
            float e0 = v0 > 0.f ? v0 : 0.2f*v0;
            float e1 = v1 > 0.f ? v1 : 0.2f*v1;
            e0 = av.x > 0 ? e0 : NEGV;
            e1 = av.y > 0 ? e1 : NEGV;
            float tm = fmaxf(e0, e1);
            #pragma unroll
            for (int o = 16; o > 0; o >>= 1)
                tm = fmaxf(tm, __shfl_xor_sync(0xffffffffu, tm, o));
            float mold = m_sh[ii];
            float mnew = fmaxf(mold, tm);
            float p0 = __expf(e0 - mnew);
            float p1 = __expf(e1 - mnew);
            float psum = p0 + p1;
            #pragma unroll
            for (int o = 16; o > 0; o >>= 1)
                psum += __shfl_xor_sync(0xffffffffu, psum, o);
            if (lane == 0) {
                float scale = __expf(mold - mnew);
                sc_sh[ii] = scale;
                l_sh[ii]  = l_sh[ii]*scale + psum;
                m_sh[ii]  = mnew;
            }
            PsT[(2*lane)*PS   + ii] = p0;
            PsT[(2*lane+1)*PS + ii] = p1;
        }
        __syncthreads();

        // rescale accumulators
        #pragma unroll
        for (int rp = 0; rp < 4; rp++) {
            ull sc2 = pack2(sc_sh[ig*8 + 2*rp], sc_sh[ig*8 + 2*rp + 1]);
            #pragma unroll
            for (int k = 0; k < 4; k++) acc[rp][k] = fmul2(acc[rp][k], sc2);
        }
        // aggregation: acc[rp][k] += (P[r0],P[r1]) * (Wh[c_k],Wh[c_k])
        const float* pbase = PsT + ig*8;
        #pragma unroll 2
        for (int jj = 0; jj < 64; jj++) {
            ull wd0 = whs_dup[jj*64 + cg];
            ull wd1 = whs_dup[jj*64 + cg + 16];
            ull wd2 = whs_dup[jj*64 + cg + 32];
            ull wd3 = whs_dup[jj*64 + cg + 48];
            #pragma unroll
            for (int rp = 0; rp < 4; rp++) {
                ull pp = *(const ull*)&pbase[jj*PS + 2*rp];
                acc[rp][0] = ffma2(wd0, pp, acc[rp][0]);
                acc[rp][1] = ffma2(wd1, pp, acc[rp][1]);
                acc[rp][2] = ffma2(wd2, pp, acc[rp][2]);
                acc[rp][3] = ffma2(wd3, pp, acc[rp][3]);
            }
        }
    }
    __syncthreads();

    if (tid < TI) {
        int r = b*NN + i0 + tid;
        g_pm[sp*ROWS_TOT + r] = m_sh[tid];
        g_pl[sp*ROWS_TOT + r] = l_sh[tid];
    }
    #pragma unroll
    for (int rp = 0; rp < 4; rp++) {
        int r0 = ig*8 + 2*rp;
        size_t base0 = ((size_t)sp*ROWS_TOT + b*NN + i0 + r0)     * HH2;
        size_t base1 = ((size_t)sp*ROWS_TOT + b*NN + i0 + r0 + 1) * HH2;
        #pragma unroll
        for (int k = 0; k < 4; k++) {
            float va, vb;
            unpack2(acc[rp][k], va, vb);
            g_pacc[base0 + cg + 16*k] = va;
            g_pacc[base1 + cg + 16*k] = vb;
        }
    }
}

// ============================================================================
// Kernel 5: combine split-K partials; normalize + elu.
// ============================================================================
__global__ void k_comb(float* __restrict__ out) {
    int tid = threadIdx.x;
    int r = blockIdx.x * 4 + (tid >> 6);
    int c = tid & 63;
    float m[SPLIT];
    float mx = -INFINITY;
    #pragma unroll
    for (int s = 0; s < SPLIT; s++) { m[s] = g_pm[s*ROWS_TOT + r]; mx = fmaxf(mx, m[s]); }
    float l = 0.f, val = 0.f;
    #pragma unroll
    for (int s = 0; s < SPLIT; s++) {
        float wgt = __expf(m[s] - mx);
        l   += wgt * g_pl[s*ROWS_TOT + r];
        val += wgt * g_pacc[((size_t)s*ROWS_TOT + r)*HH2 + c];
    }
    float z = val / l;
    out[(size_t)r*HH2 + c] = z > 0.f ? z : expm1f(z);
}

// ============================================================================
extern "C" void kernel_launch(void* const* d_in, const int* in_sizes, int n_in,
                              void* d_out, int out_size) {
    const float* hist  = (const float*)d_in[0];
    const int*   adj   = (const int*)  d_in[1];
    const float* W1    = (const float*)d_in[2];
    const float* b1    = (const float*)d_in[3];
    const float* W_ih  = (const float*)d_in[4];
    const float* W_hh  = (const float*)d_in[5];
    const float* b_ih  = (const float*)d_in[6];
    const float* b_hh  = (const float*)d_in[7];
    const float* Wg    = (const float*)d_in[8];
    const float* a_src = (const float*)d_in[9];
    const float* a_dst = (const float*)d_in[10];
    float* out = (float*)d_out;

    const size_t sm_lstm = (size_t)(64*256 + 64*21) * sizeof(float);
    const size_t sm_gat  = (size_t)(64*64*8) + (size_t)(64*PS*4);
    cudaFuncSetAttribute(k_lstm2, cudaFuncAttributeMaxDynamicSharedMemorySize, (int)sm_lstm);
    cudaFuncSetAttribute(k_gat,   cudaFuncAttributeMaxDynamicSharedMemorySize, (int)sm_gat);

    k_h1   <<<2048, 256>>>(hist, W1, b1);
    k_wx   <<<2048, 256>>>(W_ih, b_ih, b_hh);
    k_lstm2<<<128,  256, sm_lstm>>>(W_hh);
    k_wh   <<<1024, 256>>>(Wg, a_src, a_dst);
    dim3 g4(NN/TI, BB, SPLIT);
    k_gat  <<<g4, 256, sm_gat>>>(adj);
    k_comb <<<4096, 256>>>(out);
}